// round 14
// baseline (speedup 1.0000x reference)
#include <cuda_runtime.h>
#include <cuda_fp16.h>
#include <cstdint>

#define N_NODES 50000
#define N_EDGES 800000
#define D 128
#define BN_EPS 1e-3f

#define AB 272         // bytes per fp16 smem row (136 fp16, pitch)
#define WBUF 34816     // bytes per 128x136 fp16 buffer
#define SPITCH 544     // stage fp32 row pitch bytes (512 data + 32 pad)

// Scratch
__device__ float g_hidden[N_NODES * D];
__device__ float g_counts[N_NODES];
__device__ unsigned long long g_bar;   // monotone grid barrier (replay-safe)

// ---------------------------------------------------------------------------
// helpers
// ---------------------------------------------------------------------------
__device__ __forceinline__ uint32_t smem_u32(const void* p) {
    uint32_t a;
    asm("{ .reg .u64 t; cvta.to.shared.u64 t, %1; cvt.u32.u64 %0, t; }" : "=r"(a) : "l"(p));
    return a;
}

__device__ __forceinline__ void red_add_v4(float* addr, float a, float b, float c, float d) {
    asm volatile("red.global.add.v4.f32 [%0], {%1, %2, %3, %4};"
                 :: "l"(addr), "f"(a), "f"(b), "f"(c), "f"(d) : "memory");
}

__device__ __forceinline__ void ldsm_x4(uint32_t* r, uint32_t addr) {
    asm volatile("ldmatrix.sync.aligned.m8n8.x4.shared.b16 {%0,%1,%2,%3}, [%4];"
                 : "=r"(r[0]), "=r"(r[1]), "=r"(r[2]), "=r"(r[3]) : "r"(addr));
}

__device__ __forceinline__ void mma_f32acc(float* c, const uint32_t* a, const uint32_t* b) {
    asm volatile("mma.sync.aligned.m16n8k16.row.col.f32.f16.f16.f32 "
                 "{%0,%1,%2,%3}, {%4,%5,%6,%7}, {%8,%9}, {%0,%1,%2,%3};"
                 : "+f"(c[0]), "+f"(c[1]), "+f"(c[2]), "+f"(c[3])
                 : "r"(a[0]), "r"(a[1]), "r"(a[2]), "r"(a[3]), "r"(b[0]), "r"(b[1]));
}

__device__ __forceinline__ void mma_fp16acc(uint32_t* c, const uint32_t* a, const uint32_t* b) {
    asm volatile("mma.sync.aligned.m16n8k16.row.col.f16.f16.f16.f16 "
                 "{%0,%1}, {%2,%3,%4,%5}, {%6,%7}, {%0,%1};"
                 : "+r"(c[0]), "+r"(c[1])
                 : "r"(a[0]), "r"(a[1]), "r"(a[2]), "r"(a[3]), "r"(b[0]), "r"(b[1]));
}

__device__ __forceinline__ uint32_t pack_h2(__half lo, __half hi) {
    return (uint32_t)__half_as_ushort(lo) | ((uint32_t)__half_as_ushort(hi) << 16);
}

__device__ __forceinline__ float tanh_fast(float x) {
    float y; asm("tanh.approx.f32 %0, %1;" : "=f"(y) : "f"(x)); return y;
}
__device__ __forceinline__ float sigmoid_fast(float x) {
    return fmaf(tanh_fast(0.5f * x), 0.5f, 0.5f);
}

__device__ __forceinline__ void cp16(uint32_t saddr, const void* g) {
    asm volatile("cp.async.cg.shared.global [%0], [%1], 16;" :: "r"(saddr), "l"(g));
}
#define CP_COMMIT() asm volatile("cp.async.commit_group;" ::: "memory")
#define CP_WAIT0()  asm volatile("cp.async.wait_group 0;" ::: "memory")

// Grid-wide barrier. Safe: grid == #SMs, 1 CTA/SM (211KB smem) -> all CTAs
// resident in wave 1. Monotone ticket counter: each launch adds exactly
// 2*grid, so (ticket/grid+1)*grid works across graph replays without reset.
__device__ __forceinline__ void grid_sync() {
    __syncthreads();
    if (threadIdx.x == 0) {
        __threadfence();
        unsigned long long ticket = atomicAdd(&g_bar, 1ULL);
        unsigned long long target =
            (ticket / gridDim.x + 1ULL) * (unsigned long long)gridDim.x;
        unsigned long long v;
        do {
            asm volatile("ld.volatile.global.u64 %0, [%1];" : "=l"(v) : "l"(&g_bar));
        } while (v < target);
        __threadfence();
    }
    __syncthreads();
}

// ---------------------------------------------------------------------------
// Fused mega-kernel: [zero + node GEMM + W prologue] -> grid_sync ->
//                    [edge GEMM+scatter] -> grid_sync -> [finalize]
//
// 512 threads, grid = nsm, 1 CTA/SM. SMEM (EK_SMEM = 210944 B):
//   [0]      sBn[128] f32 (node bias)
//   [1024]   sBg[128]  [1536] sBf[128]
//   [2048]   sA: 2 x WBUF fp16 A buffers
//   [71680]  sW: Wg^T, Wf^T fp16 (2 x WBUF)
//   [141312] stage (69632): node phase holds Wn^T fp16 (34816); edge phase
//            uses it as the fp32 cp.async staging buffer.
// ---------------------------------------------------------------------------
#define EK_SMEM 210944
#define OFF_A   2048
#define OFF_W   71680
#define OFF_S   141312

__global__ __launch_bounds__(512, 1)
void fused_kernel(const float* __restrict__ nf,
                  const float* __restrict__ Wn, const float* __restrict__ bn_,
                  const float* __restrict__ ef,
                  const float* __restrict__ Wg, const float* __restrict__ bgp,
                  const float* __restrict__ Wf, const float* __restrict__ bfp,
                  const float* __restrict__ gamma, const float* __restrict__ beta,
                  const float* __restrict__ mean,  const float* __restrict__ var,
                  const int*   __restrict__ eidx,
                  float* __restrict__ out) {
    extern __shared__ __align__(16) char smem[];
    float* sBn  = reinterpret_cast<float*>(smem);
    float* sBg  = reinterpret_cast<float*>(smem + 1024);
    float* sBf  = reinterpret_cast<float*>(smem + 1536);
    char*  sA   = smem + OFF_A;
    char*  sW   = smem + OFF_W;
    char*  sS   = smem + OFF_S;

    const int t = threadIdx.x, w = t >> 5, lane = t & 31;
    const int wm = w & 3, wn = w >> 2;
    const int pl = lane & 1;
    const int cb = (lane & 2) * 2;
    const int bid = blockIdx.x, grid = gridDim.x;

    const uint32_t sbA = smem_u32(sA);
    const uint32_t sbW = smem_u32(sW);
    const uint32_t sbS = smem_u32(sS);

    // ldmatrix lane addressing (canonical)
    const int ra = lane & 15;
    const int ka = (lane >> 4) * 16;
    const int rb = (lane & 7) + ((lane >> 4) & 1) * 8;
    const int kb = ((lane >> 3) & 1) * 16;

    // ======================= PHASE 0: zero + node GEMM ======================
    {
        // zero out + counts
        int gid = bid * 512 + t;
        int gstride = grid * 512;
        const int nv4 = N_NODES * D / 4;
        float4 z = make_float4(0.f, 0.f, 0.f, 0.f);
        for (int i = gid; i < nv4; i += gstride)
            reinterpret_cast<float4*>(out)[i] = z;
        for (int i = gid; i < N_NODES; i += gstride)
            g_counts[i] = 0.f;
    }

    if (t < 128) { sBn[t] = bn_[t]; sBg[t] = bgp[t]; sBf[t] = bfp[t]; }

    // Load Wg/Wf into their permanent home, Wn^T into stage (temporary)
    for (int m = 0; m < 2; m++) {
        const float* W = m ? Wf : Wg;
        char* buf = sW + m * WBUF;
        for (int idx = t; idx < 16384; idx += 512) {
            int k = idx >> 7, n = idx & 127;
            *reinterpret_cast<__half*>(buf + n * AB + k * 2) = __float2half_rn(W[idx]);
        }
    }
    for (int idx = t; idx < 16384; idx += 512) {
        int k = idx >> 7, n = idx & 127;
        *reinterpret_cast<__half*>(sS + n * AB + k * 2) = __float2half_rn(Wn[idx]);
    }
    __syncthreads();

    // node GEMM: hidden = nf @ Wn + bn  (fp16 mma, fp32 acc); A in sA buf 0
    {
        const uint32_t aoffN = sbA + (uint32_t)((wm * 32 + ra) * AB + ka);
        const uint32_t boffN = sbS + (uint32_t)((wn * 32 + rb) * AB + kb);
        const int ntilesN = (N_NODES + 127) / 128;  // 391
        for (int tile = bid; tile < ntilesN; tile += grid) {
            __syncthreads();
            const int r0 = tile * 128;
            #pragma unroll
            for (int i = 0; i < 8; i++) {
                int idx = t + i * 512;
                int row = idx >> 5, c16 = idx & 31;
                int grow = r0 + row;
                float4 v = make_float4(0.f, 0.f, 0.f, 0.f);
                if (grow < N_NODES)
                    v = *reinterpret_cast<const float4*>(&nf[(size_t)grow * 128 + c16 * 4]);
                *reinterpret_cast<uint2*>(sA + row * AB + c16 * 8) = make_uint2(
                    pack_h2(__float2half_rn(v.x), __float2half_rn(v.y)),
                    pack_h2(__float2half_rn(v.z), __float2half_rn(v.w)));
            }
            __syncthreads();

            float acc[2][4][4];
            #pragma unroll
            for (int mt = 0; mt < 2; mt++)
                #pragma unroll
                for (int nt = 0; nt < 4; nt++)
                    #pragma unroll
                    for (int i = 0; i < 4; i++) acc[mt][nt][i] = 0.f;

            #pragma unroll
            for (int ks = 0; ks < 8; ks++) {
                uint32_t ah[2][4];
                ldsm_x4(ah[0], aoffN + ks * 32);
                ldsm_x4(ah[1], aoffN + 16 * AB + ks * 32);
                uint32_t bh[8];
                ldsm_x4(&bh[0], boffN + ks * 32);
                ldsm_x4(&bh[4], boffN + (uint32_t)(16 * AB) + ks * 32);
                #pragma unroll
                for (int mt = 0; mt < 2; mt++)
                    #pragma unroll
                    for (int nt = 0; nt < 4; nt++)
                        mma_f32acc(acc[mt][nt], ah[mt], &bh[nt * 2]);
            }

            #pragma unroll
            for (int mt = 0; mt < 2; mt++) {
                #pragma unroll
                for (int rr = 0; rr < 2; rr++) {
                    int grow = r0 + wm * 32 + mt * 16 + (lane >> 2) + rr * 8;
                    if (grow < N_NODES) {
                        float* hp = &g_hidden[(size_t)grow * 128];
                        #pragma unroll
                        for (int nt = 0; nt < 4; nt++) {
                            int c = wn * 32 + nt * 8 + (lane & 3) * 2;
                            float2 o;
                            o.x = acc[mt][nt][rr * 2 + 0] + sBn[c];
                            o.y = acc[mt][nt][rr * 2 + 1] + sBn[c + 1];
                            *reinterpret_cast<float2*>(hp + c) = o;
                        }
                    }
                }
            }
        }
    }

    grid_sync();   // hidden + zeroed out visible grid-wide; stage free

    // ======================= PHASE 1: edge GEMM + scatter ===================
    {
        const int ntiles = N_EDGES / 128;  // 6250
        const int tile0 = bid;

        // prefetch tile0 raw fp32 into stage
        {
            const int e0 = tile0 * 128;
            #pragma unroll
            for (int i = 0; i < 8; i++) {
                int idx = t + i * 512;
                int row = idx >> 5, c16 = idx & 31;
                cp16(sbS + (uint32_t)(row * SPITCH + c16 * 16),
                     &ef[(size_t)(e0 + row) * 128 + c16 * 4]);
            }
            CP_COMMIT();
        }
        CP_WAIT0();
        __syncthreads();

        // convert tile0 into A buffer 0
        #pragma unroll
        for (int i = 0; i < 8; i++) {
            int idx = t + i * 512;
            int row = idx >> 5, c16 = idx & 31;
            float4 v = *reinterpret_cast<const float4*>(sS + row * SPITCH + c16 * 16);
            *reinterpret_cast<uint2*>(sA + row * AB + c16 * 8) = make_uint2(
                pack_h2(__float2half_rn(v.x), __float2half_rn(v.y)),
                pack_h2(__float2half_rn(v.z), __float2half_rn(v.w)));
        }
        __syncthreads();

        // prefetch tile0+grid
        {
            int tn = tile0 + grid;
            if (tn >= ntiles) tn = tile0;
            const int en = tn * 128;
            #pragma unroll
            for (int i = 0; i < 8; i++) {
                int idx = t + i * 512;
                int row = idx >> 5, c16 = idx & 31;
                cp16(sbS + (uint32_t)(row * SPITCH + c16 * 16),
                     &ef[(size_t)(en + row) * 128 + c16 * 4]);
            }
            CP_COMMIT();
        }

        const uint32_t aoff0 = sbA + (uint32_t)((wm * 32 + ra) * AB + ka);
        const uint32_t boff  = sbW + (uint32_t)((wn * 32 + rb) * AB + kb);

        int cur = 0;
        for (int tile = tile0; tile < ntiles; tile += grid) {
            const int e0 = tile * 128;

            int srcR[2], dstR[2];
            #pragma unroll
            for (int mt = 0; mt < 2; mt++) {
                int r = wm * 32 + mt * 16 + (lane >> 2) + pl * 8;
                int2 p = *reinterpret_cast<const int2*>(&eidx[(size_t)(e0 + r) * 2]);
                srcR[mt] = p.x; dstR[mt] = p.y;
            }
            if (t < 128)
                atomicAdd(&g_counts[eidx[(size_t)(e0 + t) * 2]], 1.0f);

            const uint32_t aoff = aoff0 + (uint32_t)(cur * WBUF);
            uint32_t acc[2][2][4][2];
            #pragma unroll
            for (int m = 0; m < 2; m++)
                #pragma unroll
                for (int mt = 0; mt < 2; mt++)
                    #pragma unroll
                    for (int nt = 0; nt < 4; nt++) {
                        acc[m][mt][nt][0] = 0u; acc[m][mt][nt][1] = 0u;
                    }

            #pragma unroll
            for (int ks = 0; ks < 8; ks++) {
                uint32_t ah[2][4];
                ldsm_x4(ah[0], aoff + ks * 32);
                ldsm_x4(ah[1], aoff + 16 * AB + ks * 32);
                #pragma unroll
                for (int m = 0; m < 2; m++) {
                    uint32_t buf = boff + (uint32_t)(m * WBUF);
                    uint32_t bh[8];
                    ldsm_x4(&bh[0], buf + ks * 32);
                    ldsm_x4(&bh[4], buf + (uint32_t)(16 * AB) + ks * 32);
                    #pragma unroll
                    for (int mt = 0; mt < 2; mt++)
                        #pragma unroll
                        for (int nt = 0; nt < 4; nt++)
                            mma_fp16acc(acc[m][mt][nt], ah[mt], &bh[nt * 2]);
                }
            }

            CP_WAIT0();
            __syncthreads();

            {
                char* An = sA + (cur ^ 1) * WBUF;
                #pragma unroll
                for (int i = 0; i < 8; i++) {
                    int idx = t + i * 512;
                    int row = idx >> 5, c16 = idx & 31;
                    float4 v = *reinterpret_cast<const float4*>(sS + row * SPITCH + c16 * 16);
                    *reinterpret_cast<uint2*>(An + row * AB + c16 * 8) = make_uint2(
                        pack_h2(__float2half_rn(v.x), __float2half_rn(v.y)),
                        pack_h2(__float2half_rn(v.z), __float2half_rn(v.w)));
                }
            }
            __syncthreads();

            {
                int tn = tile + 2 * grid;
                if (tn >= ntiles) tn = tile;
                const int en = tn * 128;
                #pragma unroll
                for (int i = 0; i < 8; i++) {
                    int idx = t + i * 512;
                    int row = idx >> 5, c16 = idx & 31;
                    cp16(sbS + (uint32_t)(row * SPITCH + c16 * 16),
                         &ef[(size_t)(en + row) * 128 + c16 * 4]);
                }
                CP_COMMIT();
            }

            #pragma unroll
            for (int mt = 0; mt < 2; mt++) {
                const float* hp = &g_hidden[(size_t)dstR[mt] * 128];
                float* op = &out[(size_t)srcR[mt] * 128];
                #pragma unroll
                for (int nt = 0; nt < 4; nt++) {
                    const int C = wn * 32 + nt * 8 + cb;
                    float2 gv[2], fv[2];
                    #pragma unroll
                    for (int m = 0; m < 2; m++) {
                        uint32_t own0 = acc[m][mt][nt][0];
                        uint32_t own1 = acc[m][mt][nt][1];
                        uint32_t send = pl ? own0 : own1;
                        uint32_t recv = __shfl_xor_sync(0xffffffffu, send, 1);
                        uint32_t lo = pl ? recv : own0;
                        uint32_t hi = pl ? own1 : recv;
                        float2 flo = __half22float2(*reinterpret_cast<__half2*>(&lo));
                        float2 fhi = __half22float2(*reinterpret_cast<__half2*>(&hi));
                        if (m == 0) { gv[0] = flo; gv[1] = fhi; }
                        else        { fv[0] = flo; fv[1] = fhi; }
                    }

                    float4 nb  = *reinterpret_cast<const float4*>(hp + C);
                    float4 bg4 = *reinterpret_cast<const float4*>(sBg + C);
                    float4 bf4 = *reinterpret_cast<const float4*>(sBf + C);
                    float g0 = sigmoid_fast(gv[0].x + bg4.x);
                    float g1 = sigmoid_fast(gv[0].y + bg4.y);
                    float g2 = sigmoid_fast(gv[1].x + bg4.z);
                    float g3 = sigmoid_fast(gv[1].y + bg4.w);
                    float m0 = g0 * (fv[0].x + bf4.x) * nb.x;
                    float m1 = g1 * (fv[0].y + bf4.y) * nb.y;
                    float m2 = g2 * (fv[1].x + bf4.z) * nb.z;
                    float m3 = g3 * (fv[1].y + bf4.w) * nb.w;
                    red_add_v4(op + C, m0, m1, m2, m3);
                }
            }

            cur ^= 1;
        }
    }

    grid_sync();   // all reds + counts visible grid-wide

    // ======================= PHASE 2: finalize ==============================
    {
        int gid = bid * 512 + t;
        int gstride = grid * 512;
        const int total = N_NODES * 32;
        for (int idx = gid; idx < total; idx += gstride) {
            int node = idx >> 5;
            int q    = idx & 31;
            float inv = 1.f / fmaxf(g_counts[node], 1.f);

            float4 s  = reinterpret_cast<float4*>(out)[idx];
            float4 h  = *reinterpret_cast<const float4*>(&g_hidden[node * D + q * 4]);
            float4 mu = *reinterpret_cast<const float4*>(&mean[q * 4]);
            float4 vr = *reinterpret_cast<const float4*>(&var[q * 4]);
            float4 ga = *reinterpret_cast<const float4*>(&gamma[q * 4]);
            float4 be = *reinterpret_cast<const float4*>(&beta[q * 4]);

            float4 o;
            o.x = fmaxf((h.x + s.x * inv - mu.x) * rsqrtf(vr.x + BN_EPS) * ga.x + be.x, 0.f);
            o.y = fmaxf((h.y + s.y * inv - mu.y) * rsqrtf(vr.y + BN_EPS) * ga.y + be.y, 0.f);
            o.z = fmaxf((h.z + s.z * inv - mu.z) * rsqrtf(vr.z + BN_EPS) * ga.z + be.z, 0.f);
            o.w = fmaxf((h.w + s.w * inv - mu.w) * rsqrtf(vr.w + BN_EPS) * ga.w + be.w, 0.f);
            reinterpret_cast<float4*>(out)[idx] = o;
        }
    }
}

// ---------------------------------------------------------------------------
// launch
// ---------------------------------------------------------------------------
extern "C" void kernel_launch(void* const* d_in, const int* in_sizes, int n_in,
                              void* d_out, int out_size) {
    const float* nf    = (const float*)d_in[0];
    const float* ef    = (const float*)d_in[1];
    const float* Wn    = (const float*)d_in[2];
    const float* bn_   = (const float*)d_in[3];
    const float* Wg    = (const float*)d_in[4];
    const float* bg    = (const float*)d_in[5];
    const float* Wf    = (const float*)d_in[6];
    const float* bf    = (const float*)d_in[7];
    const float* gamma = (const float*)d_in[8];
    const float* beta  = (const float*)d_in[9];
    const float* mean  = (const float*)d_in[10];
    const float* var   = (const float*)d_in[11];
    const int*   eidx  = (const int*)d_in[12];
    float* out = (float*)d_out;

    int dev = 0, nsm = 148;
    cudaGetDevice(&dev);
    cudaDeviceGetAttribute(&nsm, cudaDevAttrMultiProcessorCount, dev);
    cudaFuncSetAttribute(fused_kernel, cudaFuncAttributeMaxDynamicSharedMemorySize, EK_SMEM);

    fused_kernel<<<nsm, 512, EK_SMEM>>>(nf, Wn, bn_, ef, Wg, bg, Wf, bf,
                                        gamma, beta, mean, var, eidx, out);
}

// round 15
// speedup vs baseline: 1.0414x; 1.0414x over previous
#include <cuda_runtime.h>
#include <cuda_fp16.h>
#include <cstdint>

#define N_NODES 50000
#define N_EDGES 800000
#define D 128
#define BN_EPS 1e-3f

#define AB 272         // bytes per fp16 smem row (136 fp16, pitch)
#define WBUF 34816     // bytes per 128x136 fp16 buffer
#define SPITCH 544     // stage fp32 row pitch bytes (512 data + 32 pad)

// Scratch
__device__ float g_hidden[N_NODES * D];
__device__ float g_counts[N_NODES];

// ---------------------------------------------------------------------------
// helpers
// ---------------------------------------------------------------------------
__device__ __forceinline__ uint32_t smem_u32(const void* p) {
    uint32_t a;
    asm("{ .reg .u64 t; cvta.to.shared.u64 t, %1; cvt.u32.u64 %0, t; }" : "=r"(a) : "l"(p));
    return a;
}

__device__ __forceinline__ void red_add_v4(float* addr, float a, float b, float c, float d) {
    asm volatile("red.global.add.v4.f32 [%0], {%1, %2, %3, %4};"
                 :: "l"(addr), "f"(a), "f"(b), "f"(c), "f"(d) : "memory");
}

__device__ __forceinline__ void ldsm_x4(uint32_t* r, uint32_t addr) {
    asm volatile("ldmatrix.sync.aligned.m8n8.x4.shared.b16 {%0,%1,%2,%3}, [%4];"
                 : "=r"(r[0]), "=r"(r[1]), "=r"(r[2]), "=r"(r[3]) : "r"(addr));
}

__device__ __forceinline__ void mma_f32acc(float* c, const uint32_t* a, const uint32_t* b) {
    asm volatile("mma.sync.aligned.m16n8k16.row.col.f32.f16.f16.f32 "
                 "{%0,%1,%2,%3}, {%4,%5,%6,%7}, {%8,%9}, {%0,%1,%2,%3};"
                 : "+f"(c[0]), "+f"(c[1]), "+f"(c[2]), "+f"(c[3])
                 : "r"(a[0]), "r"(a[1]), "r"(a[2]), "r"(a[3]), "r"(b[0]), "r"(b[1]));
}

__device__ __forceinline__ void mma_fp16acc(uint32_t* c, const uint32_t* a, const uint32_t* b) {
    asm volatile("mma.sync.aligned.m16n8k16.row.col.f16.f16.f16.f16 "
                 "{%0,%1}, {%2,%3,%4,%5}, {%6,%7}, {%0,%1};"
                 : "+r"(c[0]), "+r"(c[1])
                 : "r"(a[0]), "r"(a[1]), "r"(a[2]), "r"(a[3]), "r"(b[0]), "r"(b[1]));
}

__device__ __forceinline__ uint32_t pack_h2(__half lo, __half hi) {
    return (uint32_t)__half_as_ushort(lo) | ((uint32_t)__half_as_ushort(hi) << 16);
}

__device__ __forceinline__ float tanh_fast(float x) {
    float y; asm("tanh.approx.f32 %0, %1;" : "=f"(y) : "f"(x)); return y;
}
__device__ __forceinline__ float sigmoid_fast(float x) {
    return fmaf(tanh_fast(0.5f * x), 0.5f, 0.5f);
}

__device__ __forceinline__ void cp16(uint32_t saddr, const void* g) {
    asm volatile("cp.async.cg.shared.global [%0], [%1], 16;" :: "r"(saddr), "l"(g));
}
#define CP_COMMIT() asm volatile("cp.async.commit_group;" ::: "memory")
#define CP_WAIT0()  asm volatile("cp.async.wait_group 0;" ::: "memory")

// ---------------------------------------------------------------------------
// K1: node GEMM + fused zero (R13-passing, unchanged)
// ---------------------------------------------------------------------------
#define NG_SMEM 70656

__global__ __launch_bounds__(512, 1)
void node_gemm_kernel(const float* __restrict__ nf,
                      const float* __restrict__ W,
                      const float* __restrict__ b,
                      float* __restrict__ out) {
    extern __shared__ __align__(16) char smem[];
    float* sB = reinterpret_cast<float*>(smem);
    char*  sA = smem + 1024;
    char*  sW = smem + 35840;

    const int t = threadIdx.x, w = t >> 5, lane = t & 31;
    const int wm = w & 3, wn = w >> 2;

    {
        int gid = blockIdx.x * 512 + t;
        int gstride = gridDim.x * 512;
        const int nv4 = N_NODES * D / 4;
        float4 z = make_float4(0.f, 0.f, 0.f, 0.f);
        for (int i = gid; i < nv4; i += gstride)
            reinterpret_cast<float4*>(out)[i] = z;
        for (int i = gid; i < N_NODES; i += gstride)
            g_counts[i] = 0.f;
    }

    if (t < 128) sB[t] = b[t];

    for (int idx = t; idx < 16384; idx += 512) {
        int k = idx >> 7, n = idx & 127;
        *reinterpret_cast<__half*>(sW + n * AB + k * 2) = __float2half_rn(W[idx]);
    }
    __syncthreads();

    const uint32_t sbA = smem_u32(sA);
    const uint32_t sbW = smem_u32(sW);

    const int ra = lane & 15;
    const int ka = (lane >> 4) * 16;
    const int rb = (lane & 7) + ((lane >> 4) & 1) * 8;
    const int kb = ((lane >> 3) & 1) * 16;
    const uint32_t aoff = sbA + (uint32_t)((wm * 32 + ra) * AB + ka);
    const uint32_t boff = sbW + (uint32_t)((wn * 32 + rb) * AB + kb);

    const int ntiles = (N_NODES + 127) / 128;  // 391
    for (int tile = blockIdx.x; tile < ntiles; tile += gridDim.x) {
        __syncthreads();
        const int r0 = tile * 128;
        #pragma unroll
        for (int i = 0; i < 8; i++) {
            int idx = t + i * 512;
            int row = idx >> 5, c16 = idx & 31;
            int grow = r0 + row;
            float4 v = make_float4(0.f, 0.f, 0.f, 0.f);
            if (grow < N_NODES)
                v = *reinterpret_cast<const float4*>(&nf[(size_t)grow * 128 + c16 * 4]);
            *reinterpret_cast<uint2*>(sA + row * AB + c16 * 8) = make_uint2(
                pack_h2(__float2half_rn(v.x), __float2half_rn(v.y)),
                pack_h2(__float2half_rn(v.z), __float2half_rn(v.w)));
        }
        __syncthreads();

        float acc[2][4][4];
        #pragma unroll
        for (int mt = 0; mt < 2; mt++)
            #pragma unroll
            for (int nt = 0; nt < 4; nt++)
                #pragma unroll
                for (int i = 0; i < 4; i++) acc[mt][nt][i] = 0.f;

        #pragma unroll
        for (int ks = 0; ks < 8; ks++) {
            uint32_t ah[2][4];
            ldsm_x4(ah[0], aoff + ks * 32);
            ldsm_x4(ah[1], aoff + 16 * AB + ks * 32);
            uint32_t bh[8];
            ldsm_x4(&bh[0], boff + ks * 32);
            ldsm_x4(&bh[4], boff + (uint32_t)(16 * AB) + ks * 32);
            #pragma unroll
            for (int mt = 0; mt < 2; mt++)
                #pragma unroll
                for (int nt = 0; nt < 4; nt++)
                    mma_f32acc(acc[mt][nt], ah[mt], &bh[nt * 2]);
        }

        #pragma unroll
        for (int mt = 0; mt < 2; mt++) {
            #pragma unroll
            for (int rr = 0; rr < 2; rr++) {
                int grow = r0 + wm * 32 + mt * 16 + (lane >> 2) + rr * 8;
                if (grow < N_NODES) {
                    float* hp = &g_hidden[(size_t)grow * 128];
                    #pragma unroll
                    for (int nt = 0; nt < 4; nt++) {
                        int c = wn * 32 + nt * 8 + (lane & 3) * 2;
                        float2 o;
                        o.x = acc[mt][nt][rr * 2 + 0] + sB[c];
                        o.y = acc[mt][nt][rr * 2 + 1] + sB[c + 1];
                        *reinterpret_cast<float2*>(hp + c) = o;
                    }
                }
            }
        }
    }
}

// ---------------------------------------------------------------------------
// K2: edge kernel — 1024 threads (32 warps, 8/SMSP), warp grid 4(M) x 8(N),
//     warp tile 32x16. Same pipeline/math as R12/R13 (fp16-acc mma,
//     double-buffered A, cp.async stage, pair-exchange red.v4 epilogue).
// SMEM layout identical (210944 B), 1 CTA/SM.
// ---------------------------------------------------------------------------
#define EK_SMEM 210944
#define OFF_A   2048
#define OFF_W   71680
#define OFF_S   141312

__global__ __launch_bounds__(1024, 1)
void edge_kernel(const float* __restrict__ ef,
                 const float* __restrict__ Wg, const float* __restrict__ bgp,
                 const float* __restrict__ Wf, const float* __restrict__ bfp,
                 const int*   __restrict__ eidx,
                 float* __restrict__ out) {
    extern __shared__ __align__(16) char smem[];
    float* sBg  = reinterpret_cast<float*>(smem + 1024);
    float* sBf  = reinterpret_cast<float*>(smem + 1536);
    char*  sA   = smem + OFF_A;
    char*  sW   = smem + OFF_W;
    char*  sS   = smem + OFF_S;

    const int t = threadIdx.x, w = t >> 5, lane = t & 31;
    const int wm = w & 3, wn = w >> 2;      // wm 0..3, wn 0..7
    const int pl = lane & 1;
    const int cb = (lane & 2) * 2;

    const uint32_t sbA = smem_u32(sA);
    const uint32_t sbW = smem_u32(sW);
    const uint32_t sbS = smem_u32(sS);

    const int ntiles = N_EDGES / 128;
    const int tile0 = blockIdx.x;

    // prefetch tile0 raw fp32 into stage (4 x 16B per thread)
    {
        const int e0 = tile0 * 128;
        #pragma unroll
        for (int i = 0; i < 4; i++) {
            int idx = t + i * 1024;
            int row = idx >> 5, c16 = idx & 31;
            cp16(sbS + (uint32_t)(row * SPITCH + c16 * 16),
                 &ef[(size_t)(e0 + row) * 128 + c16 * 4]);
        }
        CP_COMMIT();
    }

    if (t < 128) { sBg[t] = bgp[t]; sBf[t] = bfp[t]; }

    for (int m = 0; m < 2; m++) {
        const float* W = m ? Wf : Wg;
        char* buf = sW + m * WBUF;
        for (int idx = t; idx < 16384; idx += 1024) {
            int k = idx >> 7, n = idx & 127;
            *reinterpret_cast<__half*>(buf + n * AB + k * 2) = __float2half_rn(W[idx]);
        }
    }
    CP_WAIT0();
    __syncthreads();

    // convert tile0 into A buffer 0
    #pragma unroll
    for (int i = 0; i < 4; i++) {
        int idx = t + i * 1024;
        int row = idx >> 5, c16 = idx & 31;
        float4 v = *reinterpret_cast<const float4*>(sS + row * SPITCH + c16 * 16);
        *reinterpret_cast<uint2*>(sA + row * AB + c16 * 8) = make_uint2(
            pack_h2(__float2half_rn(v.x), __float2half_rn(v.y)),
            pack_h2(__float2half_rn(v.z), __float2half_rn(v.w)));
    }
    __syncthreads();

    // prefetch tile0+grid
    {
        int tn = tile0 + gridDim.x;
        if (tn >= ntiles) tn = tile0;
        const int en = tn * 128;
        #pragma unroll
        for (int i = 0; i < 4; i++) {
            int idx = t + i * 1024;
            int row = idx >> 5, c16 = idx & 31;
            cp16(sbS + (uint32_t)(row * SPITCH + c16 * 16),
                 &ef[(size_t)(en + row) * 128 + c16 * 4]);
        }
        CP_COMMIT();
    }

    // ldmatrix lane addressing
    const int ra = lane & 15;
    const int ka = (lane >> 4) * 16;
    const int rb = (lane & 7) + ((lane >> 4) & 1) * 8;
    const int kb = ((lane >> 3) & 1) * 16;

    const uint32_t aoff0 = sbA + (uint32_t)((wm * 32 + ra) * AB + ka);
    const uint32_t boff  = sbW + (uint32_t)((wn * 16 + rb) * AB + kb);  // 16-row B slice

    int cur = 0;
    for (int tile = tile0; tile < ntiles; tile += gridDim.x) {
        const int e0 = tile * 128;

        int srcR[2], dstR[2];
        #pragma unroll
        for (int mt = 0; mt < 2; mt++) {
            int r = wm * 32 + mt * 16 + (lane >> 2) + pl * 8;
            int2 p = *reinterpret_cast<const int2*>(&eidx[(size_t)(e0 + r) * 2]);
            srcR[mt] = p.x; dstR[mt] = p.y;
        }
        if (t < 128)
            atomicAdd(&g_counts[eidx[(size_t)(e0 + t) * 2]], 1.0f);

        const uint32_t aoff = aoff0 + (uint32_t)(cur * WBUF);
        uint32_t acc[2][2][2][2];   // [matrix][mt][nt][reg]
        #pragma unroll
        for (int m = 0; m < 2; m++)
            #pragma unroll
            for (int mt = 0; mt < 2; mt++)
                #pragma unroll
                for (int nt = 0; nt < 2; nt++) {
                    acc[m][mt][nt][0] = 0u; acc[m][mt][nt][1] = 0u;
                }

        #pragma unroll
        for (int ks = 0; ks < 8; ks++) {
            uint32_t ah[2][4];
            ldsm_x4(ah[0], aoff + ks * 32);
            ldsm_x4(ah[1], aoff + 16 * AB + ks * 32);
            #pragma unroll
            for (int m = 0; m < 2; m++) {
                uint32_t bh[4];   // 16 B-rows -> 2 n8 tiles
                ldsm_x4(bh, boff + (uint32_t)(m * WBUF) + ks * 32);
                #pragma unroll
                for (int mt = 0; mt < 2; mt++)
                    #pragma unroll
                    for (int nt = 0; nt < 2; nt++)
                        mma_fp16acc(acc[m][mt][nt], ah[mt], &bh[nt * 2]);
            }
        }

        CP_WAIT0();
        __syncthreads();

        // convert stage -> A[nxt]
        {
            char* An = sA + (cur ^ 1) * WBUF;
            #pragma unroll
            for (int i = 0; i < 4; i++) {
                int idx = t + i * 1024;
                int row = idx >> 5, c16 = idx & 31;
                float4 v = *reinterpret_cast<const float4*>(sS + row * SPITCH + c16 * 16);
                *reinterpret_cast<uint2*>(An + row * AB + c16 * 8) = make_uint2(
                    pack_h2(__float2half_rn(v.x), __float2half_rn(v.y)),
                    pack_h2(__float2half_rn(v.z), __float2half_rn(v.w)));
            }
        }
        __syncthreads();

        // prefetch tile+2*grid
        {
            int tn = tile + 2 * gridDim.x;
            if (tn >= ntiles) tn = tile;
            const int en = tn * 128;
            #pragma unroll
            for (int i = 0; i < 4; i++) {
                int idx = t + i * 1024;
                int row = idx >> 5, c16 = idx & 31;
                cp16(sbS + (uint32_t)(row * SPITCH + c16 * 16),
                     &ef[(size_t)(en + row) * 128 + c16 * 4]);
            }
            CP_COMMIT();
        }

        // Epilogue: pair-exchange, cols C..C+3 within the 16-col warp slice
        #pragma unroll
        for (int mt = 0; mt < 2; mt++) {
            const float* hp = &g_hidden[(size_t)dstR[mt] * 128];
            float* op = &out[(size_t)srcR[mt] * 128];
            #pragma unroll
            for (int nt = 0; nt < 2; nt++) {
                const int C = wn * 16 + nt * 8 + cb;
                float2 gv[2], fv[2];
                #pragma unroll
                for (int m = 0; m < 2; m++) {
                    uint32_t own0 = acc[m][mt][nt][0];
                    uint32_t own1 = acc[m][mt][nt][1];
                    uint32_t send = pl ? own0 : own1;
                    uint32_t recv = __shfl_xor_sync(0xffffffffu, send, 1);
                    uint32_t lo = pl ? recv : own0;
                    uint32_t hi = pl ? own1 : recv;
                    float2 flo = __half22float2(*reinterpret_cast<__half2*>(&lo));
                    float2 fhi = __half22float2(*reinterpret_cast<__half2*>(&hi));
                    if (m == 0) { gv[0] = flo; gv[1] = fhi; }
                    else        { fv[0] = flo; fv[1] = fhi; }
                }

                float4 nb  = *reinterpret_cast<const float4*>(hp + C);
                float4 bg4 = *reinterpret_cast<const float4*>(sBg + C);
                float4 bf4 = *reinterpret_cast<const float4*>(sBf + C);
                float g0 = sigmoid_fast(gv[0].x + bg4.x);
                float g1 = sigmoid_fast(gv[0].y + bg4.y);
                float g2 = sigmoid_fast(gv[1].x + bg4.z);
                float g3 = sigmoid_fast(gv[1].y + bg4.w);
                float m0 = g0 * (fv[0].x + bf4.x) * nb.x;
                float m1 = g1 * (fv[0].y + bf4.y) * nb.y;
                float m2 = g2 * (fv[1].x + bf4.z) * nb.z;
                float m3 = g3 * (fv[1].y + bf4.w) * nb.w;
                red_add_v4(op + C, m0, m1, m2, m3);
            }
        }

        cur ^= 1;
    }
}

// ---------------------------------------------------------------------------
// K3: finalize (unchanged)
// ---------------------------------------------------------------------------
__global__ void finalize_kernel(const float* __restrict__ gamma,
                                const float* __restrict__ beta,
                                const float* __restrict__ mean,
                                const float* __restrict__ var,
                                float* __restrict__ out) {
    int idx = blockIdx.x * blockDim.x + threadIdx.x;
    const int total = N_NODES * 32;
    if (idx >= total) return;
    int node = idx >> 5;
    int q    = idx & 31;
    float inv = 1.f / fmaxf(g_counts[node], 1.f);

    float4 s  = reinterpret_cast<float4*>(out)[idx];
    float4 h  = *reinterpret_cast<const float4*>(&g_hidden[node * D + q * 4]);
    float4 mu = *reinterpret_cast<const float4*>(&mean[q * 4]);
    float4 vr = *reinterpret_cast<const float4*>(&var[q * 4]);
    float4 ga = *reinterpret_cast<const float4*>(&gamma[q * 4]);
    float4 be = *reinterpret_cast<const float4*>(&beta[q * 4]);

    float4 o;
    o.x = fmaxf((h.x + s.x * inv - mu.x) * rsqrtf(vr.x + BN_EPS) * ga.x + be.x, 0.f);
    o.y = fmaxf((h.y + s.y * inv - mu.y) * rsqrtf(vr.y + BN_EPS) * ga.y + be.y, 0.f);
    o.z = fmaxf((h.z + s.z * inv - mu.z) * rsqrtf(vr.z + BN_EPS) * ga.z + be.z, 0.f);
    o.w = fmaxf((h.w + s.w * inv - mu.w) * rsqrtf(vr.w + BN_EPS) * ga.w + be.w, 0.f);
    reinterpret_cast<float4*>(out)[idx] = o;
}

// ---------------------------------------------------------------------------
// launch
// ---------------------------------------------------------------------------
extern "C" void kernel_launch(void* const* d_in, const int* in_sizes, int n_in,
                              void* d_out, int out_size) {
    const float* nf    = (const float*)d_in[0];
    const float* ef    = (const float*)d_in[1];
    const float* Wn    = (const float*)d_in[2];
    const float* bn_   = (const float*)d_in[3];
    const float* Wg    = (const float*)d_in[4];
    const float* bg    = (const float*)d_in[5];
    const float* Wf    = (const float*)d_in[6];
    const float* bf    = (const float*)d_in[7];
    const float* gamma = (const float*)d_in[8];
    const float* beta  = (const float*)d_in[9];
    const float* mean  = (const float*)d_in[10];
    const float* var   = (const float*)d_in[11];
    const int*   eidx  = (const int*)d_in[12];
    float* out = (float*)d_out;

    int dev = 0, nsm = 148;
    cudaGetDevice(&dev);
    cudaDeviceGetAttribute(&nsm, cudaDevAttrMultiProcessorCount, dev);
    cudaFuncSetAttribute(node_gemm_kernel, cudaFuncAttributeMaxDynamicSharedMemorySize, NG_SMEM);
    cudaFuncSetAttribute(edge_kernel,      cudaFuncAttributeMaxDynamicSharedMemorySize, EK_SMEM);

    node_gemm_kernel<<<nsm, 512, NG_SMEM>>>(nf, Wn, bn_, out);
    edge_kernel<<<nsm, 1024, EK_SMEM>>>(ef, Wg, bg, Wf, bf, eidx, out);
    finalize_kernel<<<(N_NODES * 32 + 255) / 256, 256>>>(gamma, beta, mean, var, out);
}

// round 16
// speedup vs baseline: 1.0826x; 1.0395x over previous
#include <cuda_runtime.h>
#include <cuda_fp16.h>
#include <cstdint>

#define N_NODES 50000
#define N_EDGES 800000
#define D 128
#define BN_EPS 1e-3f

#define AB 272         // bytes per fp16 smem row (136 fp16, pitch)
#define WBUF 34816     // bytes per 128x136 fp16 buffer
#define SPITCH 544     // stage fp32 row pitch bytes (512 data + 32 pad)

// Scratch
__device__ float  g_hidden[N_NODES * D];
__device__ float  g_counts[N_NODES];
__device__ __half g_sums[N_NODES * D];   // fp16 segment-sum accumulator

// ---------------------------------------------------------------------------
// helpers
// ---------------------------------------------------------------------------
__device__ __forceinline__ uint32_t smem_u32(const void* p) {
    uint32_t a;
    asm("{ .reg .u64 t; cvta.to.shared.u64 t, %1; cvt.u32.u64 %0, t; }" : "=r"(a) : "l"(p));
    return a;
}

// fp16x2 vector reduction: 16B = 8 half adds, one L2 atomic op
__device__ __forceinline__ void red_h2_v4(__half* addr, uint32_t a, uint32_t b,
                                          uint32_t c, uint32_t d) {
    asm volatile("red.global.add.noftz.v4.f16x2 [%0], {%1, %2, %3, %4};"
                 :: "l"(addr), "r"(a), "r"(b), "r"(c), "r"(d) : "memory");
}

__device__ __forceinline__ void ldsm_x4(uint32_t* r, uint32_t addr) {
    asm volatile("ldmatrix.sync.aligned.m8n8.x4.shared.b16 {%0,%1,%2,%3}, [%4];"
                 : "=r"(r[0]), "=r"(r[1]), "=r"(r[2]), "=r"(r[3]) : "r"(addr));
}

__device__ __forceinline__ void mma_f32acc(float* c, const uint32_t* a, const uint32_t* b) {
    asm volatile("mma.sync.aligned.m16n8k16.row.col.f32.f16.f16.f32 "
                 "{%0,%1,%2,%3}, {%4,%5,%6,%7}, {%8,%9}, {%0,%1,%2,%3};"
                 : "+f"(c[0]), "+f"(c[1]), "+f"(c[2]), "+f"(c[3])
                 : "r"(a[0]), "r"(a[1]), "r"(a[2]), "r"(a[3]), "r"(b[0]), "r"(b[1]));
}

__device__ __forceinline__ void mma_fp16acc(uint32_t* c, const uint32_t* a, const uint32_t* b) {
    asm volatile("mma.sync.aligned.m16n8k16.row.col.f16.f16.f16.f16 "
                 "{%0,%1}, {%2,%3,%4,%5}, {%6,%7}, {%0,%1};"
                 : "+r"(c[0]), "+r"(c[1])
                 : "r"(a[0]), "r"(a[1]), "r"(a[2]), "r"(a[3]), "r"(b[0]), "r"(b[1]));
}

__device__ __forceinline__ uint32_t pack_h2(__half lo, __half hi) {
    return (uint32_t)__half_as_ushort(lo) | ((uint32_t)__half_as_ushort(hi) << 16);
}

__device__ __forceinline__ float tanh_fast(float x) {
    float y; asm("tanh.approx.f32 %0, %1;" : "=f"(y) : "f"(x)); return y;
}
__device__ __forceinline__ float sigmoid_fast(float x) {
    return fmaf(tanh_fast(0.5f * x), 0.5f, 0.5f);
}

__device__ __forceinline__ void cp16(uint32_t saddr, const void* g) {
    asm volatile("cp.async.cg.shared.global [%0], [%1], 16;" :: "r"(saddr), "l"(g));
}
#define CP_COMMIT() asm volatile("cp.async.commit_group;" ::: "memory")
#define CP_WAIT0()  asm volatile("cp.async.wait_group 0;" ::: "memory")

// ---------------------------------------------------------------------------
// K1: node GEMM + fused zero of g_sums/counts (R13 structure)
// ---------------------------------------------------------------------------
#define NG_SMEM 70656

__global__ __launch_bounds__(512, 1)
void node_gemm_kernel(const float* __restrict__ nf,
                      const float* __restrict__ W,
                      const float* __restrict__ b) {
    extern __shared__ __align__(16) char smem[];
    float* sB = reinterpret_cast<float*>(smem);
    char*  sA = smem + 1024;
    char*  sW = smem + 35840;

    const int t = threadIdx.x, w = t >> 5, lane = t & 31;
    const int wm = w & 3, wn = w >> 2;

    {   // zero g_sums (fp16) + counts
        int gid = blockIdx.x * 512 + t;
        int gstride = gridDim.x * 512;
        const int nu4 = N_NODES * D / 8;   // uint4 = 8 halves
        uint4 z = make_uint4(0u, 0u, 0u, 0u);
        for (int i = gid; i < nu4; i += gstride)
            reinterpret_cast<uint4*>(g_sums)[i] = z;
        for (int i = gid; i < N_NODES; i += gstride)
            g_counts[i] = 0.f;
    }

    if (t < 128) sB[t] = b[t];

    for (int idx = t; idx < 16384; idx += 512) {
        int k = idx >> 7, n = idx & 127;
        *reinterpret_cast<__half*>(sW + n * AB + k * 2) = __float2half_rn(W[idx]);
    }
    __syncthreads();

    const uint32_t sbA = smem_u32(sA);
    const uint32_t sbW = smem_u32(sW);

    const int ra = lane & 15;
    const int ka = (lane >> 4) * 16;
    const int rb = (lane & 7) + ((lane >> 4) & 1) * 8;
    const int kb = ((lane >> 3) & 1) * 16;
    const uint32_t aoff = sbA + (uint32_t)((wm * 32 + ra) * AB + ka);
    const uint32_t boff = sbW + (uint32_t)((wn * 32 + rb) * AB + kb);

    const int ntiles = (N_NODES + 127) / 128;  // 391
    for (int tile = blockIdx.x; tile < ntiles; tile += gridDim.x) {
        __syncthreads();
        const int r0 = tile * 128;
        #pragma unroll
        for (int i = 0; i < 8; i++) {
            int idx = t + i * 512;
            int row = idx >> 5, c16 = idx & 31;
            int grow = r0 + row;
            float4 v = make_float4(0.f, 0.f, 0.f, 0.f);
            if (grow < N_NODES)
                v = *reinterpret_cast<const float4*>(&nf[(size_t)grow * 128 + c16 * 4]);
            *reinterpret_cast<uint2*>(sA + row * AB + c16 * 8) = make_uint2(
                pack_h2(__float2half_rn(v.x), __float2half_rn(v.y)),
                pack_h2(__float2half_rn(v.z), __float2half_rn(v.w)));
        }
        __syncthreads();

        float acc[2][4][4];
        #pragma unroll
        for (int mt = 0; mt < 2; mt++)
            #pragma unroll
            for (int nt = 0; nt < 4; nt++)
                #pragma unroll
                for (int i = 0; i < 4; i++) acc[mt][nt][i] = 0.f;

        #pragma unroll
        for (int ks = 0; ks < 8; ks++) {
            uint32_t ah[2][4];
            ldsm_x4(ah[0], aoff + ks * 32);
            ldsm_x4(ah[1], aoff + 16 * AB + ks * 32);
            uint32_t bh[8];
            ldsm_x4(&bh[0], boff + ks * 32);
            ldsm_x4(&bh[4], boff + (uint32_t)(16 * AB) + ks * 32);
            #pragma unroll
            for (int mt = 0; mt < 2; mt++)
                #pragma unroll
                for (int nt = 0; nt < 4; nt++)
                    mma_f32acc(acc[mt][nt], ah[mt], &bh[nt * 2]);
        }

        #pragma unroll
        for (int mt = 0; mt < 2; mt++) {
            #pragma unroll
            for (int rr = 0; rr < 2; rr++) {
                int grow = r0 + wm * 32 + mt * 16 + (lane >> 2) + rr * 8;
                if (grow < N_NODES) {
                    float* hp = &g_hidden[(size_t)grow * 128];
                    #pragma unroll
                    for (int nt = 0; nt < 4; nt++) {
                        int c = wn * 32 + nt * 8 + (lane & 3) * 2;
                        float2 o;
                        o.x = acc[mt][nt][rr * 2 + 0] + sB[c];
                        o.y = acc[mt][nt][rr * 2 + 1] + sB[c + 1];
                        *reinterpret_cast<float2*>(hp + c) = o;
                    }
                }
            }
        }
    }
}

// ---------------------------------------------------------------------------
// K2: edge kernel — 1024 threads (32 warps), warp grid 4(M) x 8(N), warp
//     tile 32x16. fp16-acc mma, double-buffered A, cp.async stage.
//     NEW epilogue: native-fragment messages -> quad shfl -> ONE
//     red.v4.f16x2 per (row, 8 cols) into fp16 g_sums. Atomic ops AND
//     words halve vs fp32 red.v4.
// ---------------------------------------------------------------------------
#define EK_SMEM 210944
#define OFF_A   2048
#define OFF_W   71680
#define OFF_S   141312

__global__ __launch_bounds__(1024, 1)
void edge_kernel(const float* __restrict__ ef,
                 const float* __restrict__ Wg, const float* __restrict__ bgp,
                 const float* __restrict__ Wf, const float* __restrict__ bfp,
                 const int*   __restrict__ eidx) {
    extern __shared__ __align__(16) char smem[];
    float* sBg  = reinterpret_cast<float*>(smem + 1024);
    float* sBf  = reinterpret_cast<float*>(smem + 1536);
    char*  sA   = smem + OFF_A;
    char*  sW   = smem + OFF_W;
    char*  sS   = smem + OFF_S;

    const int t = threadIdx.x, w = t >> 5, lane = t & 31;
    const int wm = w & 3, wn = w >> 2;      // wm 0..3, wn 0..7
    const int q  = lane & 3;                // quad role

    const uint32_t sbA = smem_u32(sA);
    const uint32_t sbW = smem_u32(sW);
    const uint32_t sbS = smem_u32(sS);

    const int ntiles = N_EDGES / 128;
    const int tile0 = blockIdx.x;

    // prefetch tile0 raw fp32 into stage (4 x 16B per thread)
    {
        const int e0 = tile0 * 128;
        #pragma unroll
        for (int i = 0; i < 4; i++) {
            int idx = t + i * 1024;
            int row = idx >> 5, c16 = idx & 31;
            cp16(sbS + (uint32_t)(row * SPITCH + c16 * 16),
                 &ef[(size_t)(e0 + row) * 128 + c16 * 4]);
        }
        CP_COMMIT();
    }

    if (t < 128) { sBg[t] = bgp[t]; sBf[t] = bfp[t]; }

    for (int m = 0; m < 2; m++) {
        const float* W = m ? Wf : Wg;
        char* buf = sW + m * WBUF;
        for (int idx = t; idx < 16384; idx += 1024) {
            int k = idx >> 7, n = idx & 127;
            *reinterpret_cast<__half*>(buf + n * AB + k * 2) = __float2half_rn(W[idx]);
        }
    }
    CP_WAIT0();
    __syncthreads();

    // convert tile0 into A buffer 0
    #pragma unroll
    for (int i = 0; i < 4; i++) {
        int idx = t + i * 1024;
        int row = idx >> 5, c16 = idx & 31;
        float4 v = *reinterpret_cast<const float4*>(sS + row * SPITCH + c16 * 16);
        *reinterpret_cast<uint2*>(sA + row * AB + c16 * 8) = make_uint2(
            pack_h2(__float2half_rn(v.x), __float2half_rn(v.y)),
            pack_h2(__float2half_rn(v.z), __float2half_rn(v.w)));
    }
    __syncthreads();

    // prefetch tile0+grid
    {
        int tn = tile0 + gridDim.x;
        if (tn >= ntiles) tn = tile0;
        const int en = tn * 128;
        #pragma unroll
        for (int i = 0; i < 4; i++) {
            int idx = t + i * 1024;
            int row = idx >> 5, c16 = idx & 31;
            cp16(sbS + (uint32_t)(row * SPITCH + c16 * 16),
                 &ef[(size_t)(en + row) * 128 + c16 * 4]);
        }
        CP_COMMIT();
    }

    const int ra = lane & 15;
    const int ka = (lane >> 4) * 16;
    const int rb = (lane & 7) + ((lane >> 4) & 1) * 8;
    const int kb = ((lane >> 3) & 1) * 16;

    const uint32_t aoff0 = sbA + (uint32_t)((wm * 32 + ra) * AB + ka);
    const uint32_t boff  = sbW + (uint32_t)((wn * 16 + rb) * AB + kb);

    int cur = 0;
    for (int tile = tile0; tile < ntiles; tile += gridDim.x) {
        const int e0 = tile * 128;

        // indices for BOTH fragment rows (r, r+8) per mt
        int srcR[2][2], dstR[2][2];
        #pragma unroll
        for (int mt = 0; mt < 2; mt++) {
            int r = wm * 32 + mt * 16 + (lane >> 2);
            int2 p0 = *reinterpret_cast<const int2*>(&eidx[(size_t)(e0 + r) * 2]);
            int2 p1 = *reinterpret_cast<const int2*>(&eidx[(size_t)(e0 + r + 8) * 2]);
            srcR[mt][0] = p0.x; dstR[mt][0] = p0.y;
            srcR[mt][1] = p1.x; dstR[mt][1] = p1.y;
        }
        if (t < 128)
            atomicAdd(&g_counts[eidx[(size_t)(e0 + t) * 2]], 1.0f);

        const uint32_t aoff = aoff0 + (uint32_t)(cur * WBUF);
        uint32_t acc[2][2][2][2];   // [matrix][mt][nt][reg]
        #pragma unroll
        for (int m = 0; m < 2; m++)
            #pragma unroll
            for (int mt = 0; mt < 2; mt++)
                #pragma unroll
                for (int nt = 0; nt < 2; nt++) {
                    acc[m][mt][nt][0] = 0u; acc[m][mt][nt][1] = 0u;
                }

        #pragma unroll
        for (int ks = 0; ks < 8; ks++) {
            uint32_t ah[2][4];
            ldsm_x4(ah[0], aoff + ks * 32);
            ldsm_x4(ah[1], aoff + 16 * AB + ks * 32);
            #pragma unroll
            for (int m = 0; m < 2; m++) {
                uint32_t bh[4];
                ldsm_x4(bh, boff + (uint32_t)(m * WBUF) + ks * 32);
                #pragma unroll
                for (int mt = 0; mt < 2; mt++)
                    #pragma unroll
                    for (int nt = 0; nt < 2; nt++)
                        mma_fp16acc(acc[m][mt][nt], ah[mt], &bh[nt * 2]);
            }
        }

        CP_WAIT0();
        __syncthreads();

        // convert stage -> A[nxt]
        {
            char* An = sA + (cur ^ 1) * WBUF;
            #pragma unroll
            for (int i = 0; i < 4; i++) {
                int idx = t + i * 1024;
                int row = idx >> 5, c16 = idx & 31;
                float4 v = *reinterpret_cast<const float4*>(sS + row * SPITCH + c16 * 16);
                *reinterpret_cast<uint2*>(An + row * AB + c16 * 8) = make_uint2(
                    pack_h2(__float2half_rn(v.x), __float2half_rn(v.y)),
                    pack_h2(__float2half_rn(v.z), __float2half_rn(v.w)));
            }
        }
        __syncthreads();

        // prefetch tile+2*grid
        {
            int tn = tile + 2 * gridDim.x;
            if (tn >= ntiles) tn = tile;
            const int en = tn * 128;
            #pragma unroll
            for (int i = 0; i < 4; i++) {
                int idx = t + i * 1024;
                int row = idx >> 5, c16 = idx & 31;
                cp16(sbS + (uint32_t)(row * SPITCH + c16 * 16),
                     &ef[(size_t)(en + row) * 128 + c16 * 4]);
            }
            CP_COMMIT();
        }

        // Epilogue: messages on native fragment cols c..c+1 for rows r & r+8,
        // quad-shuffle to assemble 8-col groups, lane q0 reds row r, q1 row r+8.
        #pragma unroll
        for (int mt = 0; mt < 2; mt++) {
            #pragma unroll
            for (int nt = 0; nt < 2; nt++) {
                const int C = wn * 16 + nt * 8;
                const int c = C + q * 2;
                float2 nbr = *reinterpret_cast<const float2*>(
                    &g_hidden[(size_t)dstR[mt][0] * 128 + c]);
                float2 nbs = *reinterpret_cast<const float2*>(
                    &g_hidden[(size_t)dstR[mt][1] * 128 + c]);
                uint32_t a0 = acc[0][mt][nt][0], a1 = acc[0][mt][nt][1];
                uint32_t f0 = acc[1][mt][nt][0], f1 = acc[1][mt][nt][1];
                float2 gr = __half22float2(*reinterpret_cast<__half2*>(&a0));
                float2 gs = __half22float2(*reinterpret_cast<__half2*>(&a1));
                float2 fr = __half22float2(*reinterpret_cast<__half2*>(&f0));
                float2 fs = __half22float2(*reinterpret_cast<__half2*>(&f1));
                float bg0 = sBg[c], bg1 = sBg[c + 1];
                float bf0 = sBf[c], bf1 = sBf[c + 1];

                float m0 = sigmoid_fast(gr.x + bg0) * (fr.x + bf0) * nbr.x;
                float m1 = sigmoid_fast(gr.y + bg1) * (fr.y + bf1) * nbr.y;
                float s0 = sigmoid_fast(gs.x + bg0) * (fs.x + bf0) * nbs.x;
                float s1 = sigmoid_fast(gs.y + bg1) * (fs.y + bf1) * nbs.y;

                uint32_t M0 = pack_h2(__float2half_rn(m0), __float2half_rn(m1));
                uint32_t M1 = pack_h2(__float2half_rn(s0), __float2half_rn(s1));

                uint32_t v0[4], v1[4];
                #pragma unroll
                for (int j = 0; j < 4; j++) {
                    v0[j] = __shfl_sync(0xffffffffu, M0, j, 4);
                    v1[j] = __shfl_sync(0xffffffffu, M1, j, 4);
                }
                if (q == 0)
                    red_h2_v4(&g_sums[(size_t)srcR[mt][0] * 128 + C],
                              v0[0], v0[1], v0[2], v0[3]);
                else if (q == 1)
                    red_h2_v4(&g_sums[(size_t)srcR[mt][1] * 128 + C],
                              v1[0], v1[1], v1[2], v1[3]);
            }
        }

        cur ^= 1;
    }
}

// ---------------------------------------------------------------------------
// K3: finalize — out = relu(bn(hidden + sums/max(counts,1))), sums from fp16
// ---------------------------------------------------------------------------
__global__ void finalize_kernel(const float* __restrict__ gamma,
                                const float* __restrict__ beta,
                                const float* __restrict__ mean,
                                const float* __restrict__ var,
                                float* __restrict__ out) {
    int idx = blockIdx.x * blockDim.x + threadIdx.x;
    const int total = N_NODES * 32;
    if (idx >= total) return;
    int node = idx >> 5;
    int qq   = idx & 31;
    float inv = 1.f / fmaxf(g_counts[node], 1.f);

    uint2 sv = reinterpret_cast<const uint2*>(g_sums)[idx];
    float2 s01 = __half22float2(*reinterpret_cast<__half2*>(&sv.x));
    float2 s23 = __half22float2(*reinterpret_cast<__half2*>(&sv.y));

    float4 h  = *reinterpret_cast<const float4*>(&g_hidden[node * D + qq * 4]);
    float4 mu = *reinterpret_cast<const float4*>(&mean[qq * 4]);
    float4 vr = *reinterpret_cast<const float4*>(&var[qq * 4]);
    float4 ga = *reinterpret_cast<const float4*>(&gamma[qq * 4]);
    float4 be = *reinterpret_cast<const float4*>(&beta[qq * 4]);

    float4 o;
    o.x = fmaxf((h.x + s01.x * inv - mu.x) * rsqrtf(vr.x + BN_EPS) * ga.x + be.x, 0.f);
    o.y = fmaxf((h.y + s01.y * inv - mu.y) * rsqrtf(vr.y + BN_EPS) * ga.y + be.y, 0.f);
    o.z = fmaxf((h.z + s23.x * inv - mu.z) * rsqrtf(vr.z + BN_EPS) * ga.z + be.z, 0.f);
    o.w = fmaxf((h.w + s23.y * inv - mu.w) * rsqrtf(vr.w + BN_EPS) * ga.w + be.w, 0.f);
    reinterpret_cast<float4*>(out)[idx] = o;
}

// ---------------------------------------------------------------------------
// launch
// ---------------------------------------------------------------------------
extern "C" void kernel_launch(void* const* d_in, const int* in_sizes, int n_in,
                              void* d_out, int out_size) {
    const float* nf    = (const float*)d_in[0];
    const float* ef    = (const float*)d_in[1];
    const float* Wn    = (const float*)d_in[2];
    const float* bn_   = (const float*)d_in[3];
    const float* Wg    = (const float*)d_in[4];
    const float* bg    = (const float*)d_in[5];
    const float* Wf    = (const float*)d_in[6];
    const float* bf    = (const float*)d_in[7];
    const float* gamma = (const float*)d_in[8];
    const float* beta  = (const float*)d_in[9];
    const float* mean  = (const float*)d_in[10];
    const float* var   = (const float*)d_in[11];
    const int*   eidx  = (const int*)d_in[12];
    float* out = (float*)d_out;

    int dev = 0, nsm = 148;
    cudaGetDevice(&dev);
    cudaDeviceGetAttribute(&nsm, cudaDevAttrMultiProcessorCount, dev);
    cudaFuncSetAttribute(node_gemm_kernel, cudaFuncAttributeMaxDynamicSharedMemorySize, NG_SMEM);
    cudaFuncSetAttribute(edge_kernel,      cudaFuncAttributeMaxDynamicSharedMemorySize, EK_SMEM);

    node_gemm_kernel<<<nsm, 512, NG_SMEM>>>(nf, Wn, bn_);
    edge_kernel<<<nsm, 1024, EK_SMEM>>>(ef, Wg, bg, Wf, bf, eidx);
    finalize_kernel<<<(N_NODES * 32 + 255) / 256, 256>>>(gamma, beta, mean, var, out);
}